// round 14
// baseline (speedup 1.0000x reference)
#include <cuda_runtime.h>
#include <cuda_fp16.h>
#include <cstdint>

// out[m,n] = sum_k x[m,k]*W0[n,k] + b0[n];  M=65536, N=1024, K=1024 fp32.
// R6-best fp16 mma.sync GEMM (128x128 CTA, 8 warps 64x32, BK=64, 3 stages,
// 2 CTAs/SM). fp32->fp16 conversion of x is software-pipelined ACROSS waves:
// each CTA converts the slice for band (my_band + P), so wave w converts wave
// w+1's data while wave w's MMAs run. Bands < P self-convert (wave-1 burst).

static constexpr int Mdim = 65536;
static constexpr int Ndim = 1024;
static constexpr int Kdim = 1024;

static constexpr int BM = 128;
static constexpr int BN = 128;
static constexpr int BK = 64;             // per stage (two 32-halves)
static constexpr int NITER = Kdim / BK;   // 16
static constexpr int THREADS = 256;       // 8 warps, warp tile 64x32
static constexpr int NBANDS = Mdim / BM;  // 512
static constexpr int NCTA_N = Ndim / BN;  // 8
static constexpr int PREF   = 40;         // bands-ahead (> ~37 bands/wave)

// device scratch (no runtime allocation allowed)
__device__ __half g_xh[(size_t)Mdim * Kdim];
__device__ __half g_wh[(size_t)Ndim * Kdim];
__device__ int    g_cnt[NBANDS];

// stage layout: A0[8K] A1[8K] B0[8K] B1[8K]; each half = 128 rows x 64B
static constexpr int HALF_SZ  = 128 * 64;            // 8192
static constexpr int A_OFF    = 0;
static constexpr int B_OFF    = 2 * HALF_SZ;
static constexpr int STAGE_SZ = 4 * HALF_SZ;         // 32768
static constexpr int NSTAGE   = 3;
static constexpr int SMEM_TOTAL = NSTAGE * STAGE_SZ; // 98304 (2 CTAs: 192KB/SM)

__device__ __forceinline__ uint32_t smem_u32(const void* p) {
    uint32_t a;
    asm("{ .reg .u64 t; cvta.to.shared.u64 t, %1; cvt.u32.u64 %0, t; }" : "=r"(a) : "l"(p));
    return a;
}

__device__ __forceinline__ void cp_async16(uint32_t dst, const void* src) {
    asm volatile("cp.async.cg.shared.global [%0], [%1], 16;" :: "r"(dst), "l"(src));
}

#define LDSM4(r0, r1, r2, r3, addr)                                          \
    asm volatile("ldmatrix.sync.aligned.m8n8.x4.shared.b16 {%0,%1,%2,%3}, [%4];" \
                 : "=r"(r0), "=r"(r1), "=r"(r2), "=r"(r3) : "r"(addr))

#define MMA16816(c0, c1, c2, c3, a0, a1, a2, a3, b0, b1)                     \
    asm volatile("mma.sync.aligned.m16n8k16.row.col.f32.f16.f16.f32 "        \
                 "{%0,%1,%2,%3}, {%4,%5,%6,%7}, {%8,%9}, {%0,%1,%2,%3};"     \
                 : "+f"(c0), "+f"(c1), "+f"(c2), "+f"(c3)                    \
                 : "r"(a0), "r"(a1), "r"(a2), "r"(a3), "r"(b0), "r"(b1))

// ---------------- conv_w kernel (also zeroes band flags in block 0) --------
__global__ void __launch_bounds__(256) conv_w_kernel(const float4* __restrict__ w4) {
    if (blockIdx.x == 0) {
        g_cnt[threadIdx.x] = 0;
        g_cnt[threadIdx.x + 256] = 0;
    }
    size_t i = (size_t)blockIdx.x * blockDim.x + threadIdx.x;
    float4 f = w4[i];
    __half2 p0 = __float22half2_rn(make_float2(f.x, f.y));
    __half2 p1 = __float22half2_rn(make_float2(f.z, f.w));
    uint2 v;
    v.x = *reinterpret_cast<uint32_t*>(&p0);
    v.y = *reinterpret_cast<uint32_t*>(&p1);
    reinterpret_cast<uint2*>(g_wh)[i] = v;
}

// ---------------- GEMM kernel ----------------
// Convert 16 rows (slice `nslice` of band `b`) of x into g_xh.
__device__ __forceinline__ void convert_slice(const float* __restrict__ x,
                                              int b, int nslice, int tid) {
    const int row0 = b * BM + nslice * 16;
    const float4* src = reinterpret_cast<const float4*>(x + (size_t)row0 * Kdim);
    uint2* dst = reinterpret_cast<uint2*>(g_xh + (size_t)row0 * Kdim);
    #pragma unroll
    for (int j = 0; j < 16; j++) {                // 4096 float4 / 256 thr
        const int idx = tid + j * 256;
        float4 f = __ldcs(&src[idx]);
        __half2 p0 = __float22half2_rn(make_float2(f.x, f.y));
        __half2 p1 = __float22half2_rn(make_float2(f.z, f.w));
        uint2 v;
        v.x = *reinterpret_cast<uint32_t*>(&p0);
        v.y = *reinterpret_cast<uint32_t*>(&p1);
        dst[idx] = v;                             // .wb: consumer hits L2
    }
}

__device__ __forceinline__ void fill_stage(uint32_t s_stage, int block_m, int block_n,
                                           int k0, int tid) {
    #pragma unroll
    for (int i = 0; i < 8; i++) {
        const int region = i >> 1;                   // 0:A0 1:A1 2:B0 3:B1
        const bool isA = (region < 2);
        const int h = region & 1;
        const int sub = ((i & 1) << 8) + tid;        // 0..511
        const int row = sub >> 2;
        const int c   = sub & 3;
        const int sw  = (row >> 1) & 3;
        const uint32_t soff = (uint32_t)(row * 64 + ((c ^ sw) << 4));
        const int grow = (isA ? block_m : block_n) + row;
        const size_t g = (size_t)grow * Kdim + k0 + h * 32 + c * 8;
        const __half* src = isA ? (g_xh + g) : (g_wh + g);
        cp_async16(s_stage + region * HALF_SZ + soff, src);
    }
    asm volatile("cp.async.commit_group;" ::: "memory");
}

__global__ void __launch_bounds__(THREADS, 2)
gemm_mma_kernel(const float* __restrict__ x, const float* __restrict__ bias,
                float* __restrict__ C) {
    extern __shared__ char smem[];
    const uint32_t sbase = smem_u32(smem);

    const int tid  = threadIdx.x;
    const int lane = tid & 31;
    const int wid  = tid >> 5;
    const int wm   = wid >> 2;          // 0..1 -> rows [wm*64, +64)
    const int wn   = wid & 3;           // 0..3 -> cols [wn*32, +32)

    const int band    = blockIdx.y;
    const int block_n = blockIdx.x * BN;
    const int block_m = band * BM;

    // ---- producer phase: prefetch-ahead conversion ----
    {
        if (band + PREF < NBANDS)
            convert_slice(x, band + PREF, blockIdx.x, tid);
        if (band < PREF)
            convert_slice(x, band, blockIdx.x, tid);
        __syncthreads();
        if (tid == 0) {
            __threadfence();
            if (band + PREF < NBANDS) atomicAdd(&g_cnt[band + PREF], 1);
            if (band < PREF)          atomicAdd(&g_cnt[band], 1);
            int v;
            do {
                asm volatile("ld.global.acquire.gpu.b32 %0, [%1];"
                             : "=r"(v) : "l"(&g_cnt[band]) : "memory");
            } while (v < NCTA_N);
        }
        __syncthreads();
    }

    // hoisted bias values for this thread's columns
    const int col_base = block_n + wn * 32 + (lane & 3) * 2;
    float bvx[4], bvy[4];
    #pragma unroll
    for (int nt = 0; nt < 4; nt++) {
        bvx[nt] = __ldg(&bias[col_base + nt * 8]);
        bvy[nt] = __ldg(&bias[col_base + nt * 8 + 1]);
    }

    // per-lane ldmatrix geometry (within a 32-wide k half)
    const int aj  = lane & 7;
    const int am8 = (lane >> 3) & 1;
    const int acb = (lane >> 4) & 1;
    const int bj  = lane & 7;
    const int bkb = (lane >> 3) & 1;
    const int bn8 = (lane >> 4) & 1;

    int arow_byte[4], asw[4];
    #pragma unroll
    for (int mt = 0; mt < 4; mt++) {
        const int r = wm * 64 + mt * 16 + am8 * 8 + aj;
        arow_byte[mt] = r * 64;
        asw[mt] = (r >> 1) & 3;
    }
    int brow_byte[2], bsw[2];
    #pragma unroll
    for (int p = 0; p < 2; p++) {
        const int r = wn * 32 + p * 16 + bn8 * 8 + bj;
        brow_byte[p] = r * 64;
        bsw[p] = (r >> 1) & 3;
    }

    float acc[4][4][4];
    #pragma unroll
    for (int mt = 0; mt < 4; mt++)
        #pragma unroll
        for (int nt = 0; nt < 4; nt++)
            #pragma unroll
            for (int r = 0; r < 4; r++)
                acc[mt][nt][r] = 0.0f;

    // prologue: fill stages 0 and 1
    fill_stage(sbase + 0 * STAGE_SZ, block_m, block_n, 0, tid);
    fill_stage(sbase + 1 * STAGE_SZ, block_m, block_n, BK, tid);

    for (int it = 0; it < NITER; it++) {
        if (it < NITER - 2)
            asm volatile("cp.async.wait_group 1;" ::: "memory");
        else
            asm volatile("cp.async.wait_group 0;" ::: "memory");
        __syncthreads();

        if (it + 2 < NITER)
            fill_stage(sbase + ((it + 2) % NSTAGE) * STAGE_SZ,
                       block_m, block_n, (it + 2) * BK, tid);

        const uint32_t st = sbase + (it % NSTAGE) * STAGE_SZ;

        #pragma unroll
        for (int h = 0; h < 2; h++) {
            const uint32_t sa = st + A_OFF + h * HALF_SZ;
            const uint32_t sb = st + B_OFF + h * HALF_SZ;
            #pragma unroll
            for (int s = 0; s < 2; s++) {
                uint32_t ah[4][4], bh[4][2];
                #pragma unroll
                for (int mt = 0; mt < 4; mt++) {
                    const uint32_t aoff =
                        arow_byte[mt] + (((s * 2 + acb) ^ asw[mt]) << 4);
                    LDSM4(ah[mt][0], ah[mt][1], ah[mt][2], ah[mt][3], sa + aoff);
                }
                #pragma unroll
                for (int p = 0; p < 2; p++) {
                    const uint32_t boff =
                        brow_byte[p] + (((s * 2 + bkb) ^ bsw[p]) << 4);
                    LDSM4(bh[2 * p][0], bh[2 * p][1],
                          bh[2 * p + 1][0], bh[2 * p + 1][1], sb + boff);
                }
                #pragma unroll
                for (int mt = 0; mt < 4; mt++)
                    #pragma unroll
                    for (int nt = 0; nt < 4; nt++) {
                        float* c = acc[mt][nt];
                        MMA16816(c[0], c[1], c[2], c[3],
                                 ah[mt][0], ah[mt][1], ah[mt][2], ah[mt][3],
                                 bh[nt][0], bh[nt][1]);
                    }
            }
        }
    }

    // epilogue: streaming global stores with bias
    const int row_base = block_m + wm * 64 + (lane >> 2);
    #pragma unroll
    for (int nt = 0; nt < 4; nt++) {
        const int col = col_base + nt * 8;
        #pragma unroll
        for (int mt = 0; mt < 4; mt++) {
            const int r0 = row_base + mt * 16;
            float2 v0 = make_float2(acc[mt][nt][0] + bvx[nt], acc[mt][nt][1] + bvy[nt]);
            float2 v1 = make_float2(acc[mt][nt][2] + bvx[nt], acc[mt][nt][3] + bvy[nt]);
            __stcs(reinterpret_cast<float2*>(C + (size_t)r0 * Ndim + col), v0);
            __stcs(reinterpret_cast<float2*>(C + (size_t)(r0 + 8) * Ndim + col), v1);
        }
    }
}

// ---------------- launch ----------------
extern "C" void kernel_launch(void* const* d_in, const int* in_sizes, int n_in,
                              void* d_out, int out_size) {
    const float* x = (const float*)d_in[0];
    const float* W = (const float*)d_in[2];  // adaptor 0 slab
    const float* b = (const float*)d_in[3];  // adaptor 0 bias
    float* out = (float*)d_out;

    cudaFuncSetAttribute(gemm_mma_kernel,
                         cudaFuncAttributeMaxDynamicSharedMemorySize, SMEM_TOTAL);

    conv_w_kernel<<<((size_t)Ndim * Kdim / 4) / 256, 256>>>((const float4*)W);

    dim3 grid(NCTA_N, NBANDS);  // (8, 512), n fastest
    gemm_mma_kernel<<<grid, THREADS, SMEM_TOTAL>>>(x, b, out);
}

// round 15
// speedup vs baseline: 1.0519x; 1.0519x over previous
#include <cuda_runtime.h>
#include <cuda_fp16.h>
#include <cstdint>

// out[m,n] = sum_k x[m,k]*W0[n,k] + b0[n];  M=65536, N=1024, K=1024 fp32.
// Best-known config: R6/R9 fp16 mma.sync GEMM (128x128 CTA, 8 warps 64x32,
// BK=64, 3 stages, 2 CTAs/SM) + single merged conversion kernel (x and W)
// with MLP-2 grid-stride loop on one persistent wave.

static constexpr int Mdim = 65536;
static constexpr int Ndim = 1024;
static constexpr int Kdim = 1024;

static constexpr int BM = 128;
static constexpr int BN = 128;
static constexpr int BK = 64;             // per stage (two 32-halves)
static constexpr int NITER = Kdim / BK;   // 16
static constexpr int THREADS = 256;       // 8 warps, warp tile 64x32

// device scratch (no runtime allocation allowed)
__device__ __half g_xh[(size_t)Mdim * Kdim];
__device__ __half g_wh[(size_t)Ndim * Kdim];

// stage layout: A0[8K] A1[8K] B0[8K] B1[8K]; each half = 128 rows x 64B
static constexpr int HALF_SZ  = 128 * 64;            // 8192
static constexpr int A_OFF    = 0;
static constexpr int B_OFF    = 2 * HALF_SZ;
static constexpr int STAGE_SZ = 4 * HALF_SZ;         // 32768
static constexpr int NSTAGE   = 3;
static constexpr int SMEM_TOTAL = NSTAGE * STAGE_SZ; // 98304 (2 CTAs: 192KB/SM)

__device__ __forceinline__ uint32_t smem_u32(const void* p) {
    uint32_t a;
    asm("{ .reg .u64 t; cvta.to.shared.u64 t, %1; cvt.u32.u64 %0, t; }" : "=r"(a) : "l"(p));
    return a;
}

__device__ __forceinline__ void cp_async16(uint32_t dst, const void* src) {
    asm volatile("cp.async.cg.shared.global [%0], [%1], 16;" :: "r"(dst), "l"(src));
}

#define LDSM4(r0, r1, r2, r3, addr)                                          \
    asm volatile("ldmatrix.sync.aligned.m8n8.x4.shared.b16 {%0,%1,%2,%3}, [%4];" \
                 : "=r"(r0), "=r"(r1), "=r"(r2), "=r"(r3) : "r"(addr))

#define MMA16816(c0, c1, c2, c3, a0, a1, a2, a3, b0, b1)                     \
    asm volatile("mma.sync.aligned.m16n8k16.row.col.f32.f16.f16.f32 "        \
                 "{%0,%1,%2,%3}, {%4,%5,%6,%7}, {%8,%9}, {%0,%1,%2,%3};"     \
                 : "+f"(c0), "+f"(c1), "+f"(c2), "+f"(c3)                    \
                 : "r"(a0), "r"(a1), "r"(a2), "r"(a3), "r"(b0), "r"(b1))

// ---------------- merged convert kernel (fp32 -> fp16) ----------------
// Blocks [0, XBLOCKS): grid-stride over x with MLP-2 unroll.
// Blocks [XBLOCKS, XBLOCKS+WBLOCKS): convert W (256K float4, 16 per thread).
static constexpr int XBLOCKS = 592;   // one persistent wave (4 x 512 thr / SM)
static constexpr int WBLOCKS = 32;

__device__ __forceinline__ uint2 cvt4(float4 f) {
    __half2 p0 = __float22half2_rn(make_float2(f.x, f.y));
    __half2 p1 = __float22half2_rn(make_float2(f.z, f.w));
    uint2 v;
    v.x = *reinterpret_cast<uint32_t*>(&p0);
    v.y = *reinterpret_cast<uint32_t*>(&p1);
    return v;
}

__global__ void __launch_bounds__(512) conv_all_kernel(const float4* __restrict__ x4,
                                                       const float4* __restrict__ w4) {
    if (blockIdx.x < XBLOCKS) {
        const size_t nthr   = (size_t)XBLOCKS * 512;
        const size_t stride = 2 * nthr;
        const size_t total  = (size_t)Mdim * Kdim / 4;   // 16,777,216
        uint2* dst = reinterpret_cast<uint2*>(g_xh);
        size_t i = (size_t)blockIdx.x * 512 + threadIdx.x;
        for (; i + nthr < total; i += stride) {
            // two independent loads in flight (MLP 2)
            float4 f0 = __ldcs(&x4[i]);
            float4 f1 = __ldcs(&x4[i + nthr]);
            __stcs(&dst[i], cvt4(f0));
            __stcs(&dst[i + nthr], cvt4(f1));
        }
        if (i < total) {
            float4 f0 = __ldcs(&x4[i]);
            __stcs(&dst[i], cvt4(f0));
        }
    } else {
        // W: 262,144 float4 over 32 blocks x 512 threads = 16 each
        const size_t base = (size_t)(blockIdx.x - XBLOCKS) * 512 + threadIdx.x;
        const size_t nthr = (size_t)WBLOCKS * 512;
        uint2* dst = reinterpret_cast<uint2*>(g_wh);
        #pragma unroll
        for (int j = 0; j < 16; j++) {
            const size_t i = base + (size_t)j * nthr;
            dst[i] = cvt4(w4[i]);   // .wb: W stays L2-resident (2MB)
        }
    }
}

// ---------------- GEMM kernel ----------------
__device__ __forceinline__ void fill_stage(uint32_t s_stage, int block_m, int block_n,
                                           int k0, int tid) {
    #pragma unroll
    for (int i = 0; i < 8; i++) {
        const int region = i >> 1;                   // 0:A0 1:A1 2:B0 3:B1
        const bool isA = (region < 2);
        const int h = region & 1;
        const int sub = ((i & 1) << 8) + tid;        // 0..511
        const int row = sub >> 2;
        const int c   = sub & 3;
        const int sw  = (row >> 1) & 3;
        const uint32_t soff = (uint32_t)(row * 64 + ((c ^ sw) << 4));
        const int grow = (isA ? block_m : block_n) + row;
        const size_t g = (size_t)grow * Kdim + k0 + h * 32 + c * 8;
        const __half* src = isA ? (g_xh + g) : (g_wh + g);
        cp_async16(s_stage + region * HALF_SZ + soff, src);
    }
    asm volatile("cp.async.commit_group;" ::: "memory");
}

__global__ void __launch_bounds__(THREADS, 2)
gemm_mma_kernel(const float* __restrict__ bias, float* __restrict__ C) {
    extern __shared__ char smem[];
    const uint32_t sbase = smem_u32(smem);

    const int tid  = threadIdx.x;
    const int lane = tid & 31;
    const int wid  = tid >> 5;
    const int wm   = wid >> 2;          // 0..1 -> rows [wm*64, +64)
    const int wn   = wid & 3;           // 0..3 -> cols [wn*32, +32)

    const int block_n = blockIdx.x * BN;
    const int block_m = blockIdx.y * BM;

    // hoisted bias values for this thread's columns
    const int col_base = block_n + wn * 32 + (lane & 3) * 2;
    float bvx[4], bvy[4];
    #pragma unroll
    for (int nt = 0; nt < 4; nt++) {
        bvx[nt] = __ldg(&bias[col_base + nt * 8]);
        bvy[nt] = __ldg(&bias[col_base + nt * 8 + 1]);
    }

    // per-lane ldmatrix geometry (within a 32-wide k half)
    const int aj  = lane & 7;
    const int am8 = (lane >> 3) & 1;
    const int acb = (lane >> 4) & 1;
    const int bj  = lane & 7;
    const int bkb = (lane >> 3) & 1;
    const int bn8 = (lane >> 4) & 1;

    int arow_byte[4], asw[4];
    #pragma unroll
    for (int mt = 0; mt < 4; mt++) {
        const int r = wm * 64 + mt * 16 + am8 * 8 + aj;
        arow_byte[mt] = r * 64;
        asw[mt] = (r >> 1) & 3;
    }
    int brow_byte[2], bsw[2];
    #pragma unroll
    for (int p = 0; p < 2; p++) {
        const int r = wn * 32 + p * 16 + bn8 * 8 + bj;
        brow_byte[p] = r * 64;
        bsw[p] = (r >> 1) & 3;
    }

    float acc[4][4][4];
    #pragma unroll
    for (int mt = 0; mt < 4; mt++)
        #pragma unroll
        for (int nt = 0; nt < 4; nt++)
            #pragma unroll
            for (int r = 0; r < 4; r++)
                acc[mt][nt][r] = 0.0f;

    // prologue: fill stages 0 and 1
    fill_stage(sbase + 0 * STAGE_SZ, block_m, block_n, 0, tid);
    fill_stage(sbase + 1 * STAGE_SZ, block_m, block_n, BK, tid);

    for (int it = 0; it < NITER; it++) {
        if (it < NITER - 2)
            asm volatile("cp.async.wait_group 1;" ::: "memory");
        else
            asm volatile("cp.async.wait_group 0;" ::: "memory");
        __syncthreads();   // orders iter it-1's reads of stage (it+2)%3 vs refill

        if (it + 2 < NITER)
            fill_stage(sbase + ((it + 2) % NSTAGE) * STAGE_SZ,
                       block_m, block_n, (it + 2) * BK, tid);

        const uint32_t st = sbase + (it % NSTAGE) * STAGE_SZ;

        #pragma unroll
        for (int h = 0; h < 2; h++) {
            const uint32_t sa = st + A_OFF + h * HALF_SZ;
            const uint32_t sb = st + B_OFF + h * HALF_SZ;
            #pragma unroll
            for (int s = 0; s < 2; s++) {
                uint32_t ah[4][4], bh[4][2];
                #pragma unroll
                for (int mt = 0; mt < 4; mt++) {
                    const uint32_t aoff =
                        arow_byte[mt] + (((s * 2 + acb) ^ asw[mt]) << 4);
                    LDSM4(ah[mt][0], ah[mt][1], ah[mt][2], ah[mt][3], sa + aoff);
                }
                #pragma unroll
                for (int p = 0; p < 2; p++) {
                    const uint32_t boff =
                        brow_byte[p] + (((s * 2 + bkb) ^ bsw[p]) << 4);
                    LDSM4(bh[2 * p][0], bh[2 * p][1],
                          bh[2 * p + 1][0], bh[2 * p + 1][1], sb + boff);
                }
                #pragma unroll
                for (int mt = 0; mt < 4; mt++)
                    #pragma unroll
                    for (int nt = 0; nt < 4; nt++) {
                        float* c = acc[mt][nt];
                        MMA16816(c[0], c[1], c[2], c[3],
                                 ah[mt][0], ah[mt][1], ah[mt][2], ah[mt][3],
                                 bh[nt][0], bh[nt][1]);
                    }
            }
        }
    }

    // epilogue: streaming global stores with bias
    const int row_base = block_m + wm * 64 + (lane >> 2);
    #pragma unroll
    for (int nt = 0; nt < 4; nt++) {
        const int col = col_base + nt * 8;
        #pragma unroll
        for (int mt = 0; mt < 4; mt++) {
            const int r0 = row_base + mt * 16;
            float2 v0 = make_float2(acc[mt][nt][0] + bvx[nt], acc[mt][nt][1] + bvy[nt]);
            float2 v1 = make_float2(acc[mt][nt][2] + bvx[nt], acc[mt][nt][3] + bvy[nt]);
            __stcs(reinterpret_cast<float2*>(C + (size_t)r0 * Ndim + col), v0);
            __stcs(reinterpret_cast<float2*>(C + (size_t)(r0 + 8) * Ndim + col), v1);
        }
    }
}

// ---------------- launch ----------------
extern "C" void kernel_launch(void* const* d_in, const int* in_sizes, int n_in,
                              void* d_out, int out_size) {
    const float* x = (const float*)d_in[0];
    const float* W = (const float*)d_in[2];  // adaptor 0 slab
    const float* b = (const float*)d_in[3];  // adaptor 0 bias
    float* out = (float*)d_out;

    cudaFuncSetAttribute(gemm_mma_kernel,
                         cudaFuncAttributeMaxDynamicSharedMemorySize, SMEM_TOTAL);

    conv_all_kernel<<<XBLOCKS + WBLOCKS, 512>>>((const float4*)x, (const float4*)W);

    dim3 grid(Ndim / BN, Mdim / BM);  // (8, 512), n fastest for L2 reuse
    gemm_mma_kernel<<<grid, THREADS, SMEM_TOTAL>>>(b, out);
}

// round 16
// speedup vs baseline: 1.1258x; 1.0703x over previous
#include <cuda_runtime.h>
#include <cuda_fp16.h>
#include <cstdint>

// out[m,n] = sum_k x[m,k]*W0[n,k] + b0[n];  M=65536, N=1024, K=1024 fp32.
// R15 config (fp16 mma.sync, 128x128 CTA, 8 warps 64x32, BK=64, 3 stages,
// 2 CTAs/SM, merged conv kernel) + cp.async issue spread across the 4 MMA
// substeps to avoid L1tex wavefront-queue bursts ahead of LDSM.

static constexpr int Mdim = 65536;
static constexpr int Ndim = 1024;
static constexpr int Kdim = 1024;

static constexpr int BM = 128;
static constexpr int BN = 128;
static constexpr int BK = 64;             // per stage (two 32-halves)
static constexpr int NITER = Kdim / BK;   // 16
static constexpr int THREADS = 256;       // 8 warps, warp tile 64x32

// device scratch (no runtime allocation allowed)
__device__ __half g_xh[(size_t)Mdim * Kdim];
__device__ __half g_wh[(size_t)Ndim * Kdim];

// stage layout: A0[8K] A1[8K] B0[8K] B1[8K]; each half = 128 rows x 64B
static constexpr int HALF_SZ  = 128 * 64;            // 8192
static constexpr int A_OFF    = 0;
static constexpr int B_OFF    = 2 * HALF_SZ;
static constexpr int STAGE_SZ = 4 * HALF_SZ;         // 32768
static constexpr int NSTAGE   = 3;
static constexpr int SMEM_TOTAL = NSTAGE * STAGE_SZ; // 98304 (2 CTAs: 192KB/SM)

__device__ __forceinline__ uint32_t smem_u32(const void* p) {
    uint32_t a;
    asm("{ .reg .u64 t; cvta.to.shared.u64 t, %1; cvt.u32.u64 %0, t; }" : "=r"(a) : "l"(p));
    return a;
}

__device__ __forceinline__ void cp_async16(uint32_t dst, const void* src) {
    asm volatile("cp.async.cg.shared.global [%0], [%1], 16;" :: "r"(dst), "l"(src));
}

#define LDSM4(r0, r1, r2, r3, addr)                                          \
    asm volatile("ldmatrix.sync.aligned.m8n8.x4.shared.b16 {%0,%1,%2,%3}, [%4];" \
                 : "=r"(r0), "=r"(r1), "=r"(r2), "=r"(r3) : "r"(addr))

#define MMA16816(c0, c1, c2, c3, a0, a1, a2, a3, b0, b1)                     \
    asm volatile("mma.sync.aligned.m16n8k16.row.col.f32.f16.f16.f32 "        \
                 "{%0,%1,%2,%3}, {%4,%5,%6,%7}, {%8,%9}, {%0,%1,%2,%3};"     \
                 : "+f"(c0), "+f"(c1), "+f"(c2), "+f"(c3)                    \
                 : "r"(a0), "r"(a1), "r"(a2), "r"(a3), "r"(b0), "r"(b1))

// ---------------- merged convert kernel (fp32 -> fp16) ----------------
static constexpr int XBLOCKS = 592;
static constexpr int WBLOCKS = 32;

__device__ __forceinline__ uint2 cvt4(float4 f) {
    __half2 p0 = __float22half2_rn(make_float2(f.x, f.y));
    __half2 p1 = __float22half2_rn(make_float2(f.z, f.w));
    uint2 v;
    v.x = *reinterpret_cast<uint32_t*>(&p0);
    v.y = *reinterpret_cast<uint32_t*>(&p1);
    return v;
}

__global__ void __launch_bounds__(512) conv_all_kernel(const float4* __restrict__ x4,
                                                       const float4* __restrict__ w4) {
    if (blockIdx.x < XBLOCKS) {
        const size_t nthr   = (size_t)XBLOCKS * 512;
        const size_t stride = 2 * nthr;
        const size_t total  = (size_t)Mdim * Kdim / 4;
        uint2* dst = reinterpret_cast<uint2*>(g_xh);
        size_t i = (size_t)blockIdx.x * 512 + threadIdx.x;
        for (; i + nthr < total; i += stride) {
            float4 f0 = __ldcs(&x4[i]);
            float4 f1 = __ldcs(&x4[i + nthr]);
            __stcs(&dst[i], cvt4(f0));
            __stcs(&dst[i + nthr], cvt4(f1));
        }
        if (i < total) {
            float4 f0 = __ldcs(&x4[i]);
            __stcs(&dst[i], cvt4(f0));
        }
    } else {
        const size_t base = (size_t)(blockIdx.x - XBLOCKS) * 512 + threadIdx.x;
        const size_t nthr = (size_t)WBLOCKS * 512;
        uint2* dst = reinterpret_cast<uint2*>(g_wh);
        #pragma unroll
        for (int j = 0; j < 16; j++) {
            const size_t i = base + (size_t)j * nthr;
            dst[i] = cvt4(w4[i]);   // .wb: W stays L2-resident
        }
    }
}

// ---------------- GEMM kernel ----------------
// Fill ONE region (2 cp.async per thread): region 0:A0 1:A1 2:B0 3:B1.
__device__ __forceinline__ void fill_region(uint32_t s_stage, int region,
                                            int block_m, int block_n,
                                            int k0, int tid) {
    const bool isA = (region < 2);
    const int h = region & 1;
    #pragma unroll
    for (int i = 0; i < 2; i++) {
        const int sub = (i << 8) + tid;          // 0..511
        const int row = sub >> 2;
        const int c   = sub & 3;
        const int sw  = (row >> 1) & 3;
        const uint32_t soff = (uint32_t)(row * 64 + ((c ^ sw) << 4));
        const int grow = (isA ? block_m : block_n) + row;
        const size_t g = (size_t)grow * Kdim + k0 + h * 32 + c * 8;
        const __half* src = isA ? (g_xh + g) : (g_wh + g);
        cp_async16(s_stage + region * HALF_SZ + soff, src);
    }
}

__device__ __forceinline__ void fill_stage_all(uint32_t s_stage, int block_m,
                                               int block_n, int k0, int tid) {
    #pragma unroll
    for (int r = 0; r < 4; r++)
        fill_region(s_stage, r, block_m, block_n, k0, tid);
    asm volatile("cp.async.commit_group;" ::: "memory");
}

__global__ void __launch_bounds__(THREADS, 2)
gemm_mma_kernel(const float* __restrict__ bias, float* __restrict__ C) {
    extern __shared__ char smem[];
    const uint32_t sbase = smem_u32(smem);

    const int tid  = threadIdx.x;
    const int lane = tid & 31;
    const int wid  = tid >> 5;
    const int wm   = wid >> 2;          // 0..1 -> rows [wm*64, +64)
    const int wn   = wid & 3;           // 0..3 -> cols [wn*32, +32)

    const int block_n = blockIdx.x * BN;
    const int block_m = blockIdx.y * BM;

    // hoisted bias values for this thread's columns
    const int col_base = block_n + wn * 32 + (lane & 3) * 2;
    float bvx[4], bvy[4];
    #pragma unroll
    for (int nt = 0; nt < 4; nt++) {
        bvx[nt] = __ldg(&bias[col_base + nt * 8]);
        bvy[nt] = __ldg(&bias[col_base + nt * 8 + 1]);
    }

    // per-lane ldmatrix geometry (within a 32-wide k half)
    const int aj  = lane & 7;
    const int am8 = (lane >> 3) & 1;
    const int acb = (lane >> 4) & 1;
    const int bj  = lane & 7;
    const int bkb = (lane >> 3) & 1;
    const int bn8 = (lane >> 4) & 1;

    int arow_byte[4], asw[4];
    #pragma unroll
    for (int mt = 0; mt < 4; mt++) {
        const int r = wm * 64 + mt * 16 + am8 * 8 + aj;
        arow_byte[mt] = r * 64;
        asw[mt] = (r >> 1) & 3;
    }
    int brow_byte[2], bsw[2];
    #pragma unroll
    for (int p = 0; p < 2; p++) {
        const int r = wn * 32 + p * 16 + bn8 * 8 + bj;
        brow_byte[p] = r * 64;
        bsw[p] = (r >> 1) & 3;
    }

    float acc[4][4][4];
    #pragma unroll
    for (int mt = 0; mt < 4; mt++)
        #pragma unroll
        for (int nt = 0; nt < 4; nt++)
            #pragma unroll
            for (int r = 0; r < 4; r++)
                acc[mt][nt][r] = 0.0f;

    // prologue: fill stages 0 and 1
    fill_stage_all(sbase + 0 * STAGE_SZ, block_m, block_n, 0, tid);
    fill_stage_all(sbase + 1 * STAGE_SZ, block_m, block_n, BK, tid);

    for (int it = 0; it < NITER; it++) {
        if (it < NITER - 2)
            asm volatile("cp.async.wait_group 1;" ::: "memory");
        else
            asm volatile("cp.async.wait_group 0;" ::: "memory");
        __syncthreads();   // orders iter it-1's reads of stage (it+2)%3 vs refill

        const bool do_fill = (it + 2 < NITER);
        const uint32_t snext = sbase + ((it + 2) % NSTAGE) * STAGE_SZ;
        const int knext = (it + 2) * BK;

        const uint32_t st = sbase + (it % NSTAGE) * STAGE_SZ;

        // 4 substeps u = (h<<1)|s; cp.async for region u interleaved after LDSM
        #pragma unroll
        for (int u = 0; u < 4; u++) {
            const int h = u >> 1;
            const int s = u & 1;
            const uint32_t sa = st + A_OFF + h * HALF_SZ;
            const uint32_t sb = st + B_OFF + h * HALF_SZ;

            uint32_t ah[4][4], bh[4][2];
            #pragma unroll
            for (int mt = 0; mt < 4; mt++) {
                const uint32_t aoff =
                    arow_byte[mt] + (((s * 2 + acb) ^ asw[mt]) << 4);
                LDSM4(ah[mt][0], ah[mt][1], ah[mt][2], ah[mt][3], sa + aoff);
            }
            #pragma unroll
            for (int p = 0; p < 2; p++) {
                const uint32_t boff =
                    brow_byte[p] + (((s * 2 + bkb) ^ bsw[p]) << 4);
                LDSM4(bh[2 * p][0], bh[2 * p][1],
                      bh[2 * p + 1][0], bh[2 * p + 1][1], sb + boff);
            }

            // spread the next-stage fill: one region per substep
            if (do_fill) {
                fill_region(snext, u, block_m, block_n, knext, tid);
                if (u == 3)
                    asm volatile("cp.async.commit_group;" ::: "memory");
            }

            #pragma unroll
            for (int mt = 0; mt < 4; mt++)
                #pragma unroll
                for (int nt = 0; nt < 4; nt++) {
                    float* c = acc[mt][nt];
                    MMA16816(c[0], c[1], c[2], c[3],
                             ah[mt][0], ah[mt][1], ah[mt][2], ah[mt][3],
                             bh[nt][0], bh[nt][1]);
                }
        }
    }

    // epilogue: streaming global stores with bias
    const int row_base = block_m + wm * 64 + (lane >> 2);
    #pragma unroll
    for (int nt = 0; nt < 4; nt++) {
        const int col = col_base + nt * 8;
        #pragma unroll
        for (int mt = 0; mt < 4; mt++) {
            const int r0 = row_base + mt * 16;
            float2 v0 = make_float2(acc[mt][nt][0] + bvx[nt], acc[mt][nt][1] + bvy[nt]);
            float2 v1 = make_float2(acc[mt][nt][2] + bvx[nt], acc[mt][nt][3] + bvy[nt]);
            __stcs(reinterpret_cast<float2*>(C + (size_t)r0 * Ndim + col), v0);
            __stcs(reinterpret_cast<float2*>(C + (size_t)(r0 + 8) * Ndim + col), v1);
        }
    }
}

// ---------------- launch ----------------
extern "C" void kernel_launch(void* const* d_in, const int* in_sizes, int n_in,
                              void* d_out, int out_size) {
    const float* x = (const float*)d_in[0];
    const float* W = (const float*)d_in[2];  // adaptor 0 slab
    const float* b = (const float*)d_in[3];  // adaptor 0 bias
    float* out = (float*)d_out;

    cudaFuncSetAttribute(gemm_mma_kernel,
                         cudaFuncAttributeMaxDynamicSharedMemorySize, SMEM_TOTAL);

    conv_all_kernel<<<XBLOCKS + WBLOCKS, 512>>>((const float4*)x, (const float4*)W);

    dim3 grid(Ndim / BN, Mdim / BM);  // (8, 512), n fastest for L2 reuse
    gemm_mma_kernel<<<grid, THREADS, SMEM_TOTAL>>>(b, out);
}